// round 8
// baseline (speedup 1.0000x reference)
#include <cuda_runtime.h>
#include <cuda_bf16.h>
#include <math.h>

// Problem constants
#define BATCH 256
#define HID   768
#define G4    3072          // 4 * HID
#define TLEN  100
#define OUTD  72
#define SRCL  16
#define BH    (BATCH * HID) // 196608
#define CH    32            // K-chunk per smem stage

// -------- device scratch (allocation-free: __device__ globals) --------
static __device__ float g_W0pack[1536 * 3072]; // packed [Wih|Whh] : [k][jt*96 + g*24 + jj]
static __device__ float g_Wcpack[768 * 3072];  // packed (Wih+Whh) : same col layout
static __device__ float g_A0[BATCH * 1536];    // [x0 | h0]
static __device__ float g_C[BATCH * HID];      // cell state
static __device__ float g_H[TLEN * BATCH * HID]; // h history (GEMM A for next step)
static __device__ float g_biasP[G4];           // packed (b_ih + b_hh), same col layout as W

// -------- f32x2 packed-math helpers (B300: 2x fp32 throughput) --------
__device__ __forceinline__ unsigned long long pack2(float x, float y) {
    unsigned long long r;
    asm("mov.b64 %0, {%1, %2};" : "=l"(r) : "f"(x), "f"(y));
    return r;
}
__device__ __forceinline__ void unpack2(unsigned long long v, float& x, float& y) {
    asm("mov.b64 {%0, %1}, %2;" : "=f"(x), "=f"(y) : "l"(v));
}
__device__ __forceinline__ void fma2(unsigned long long& d,
                                     unsigned long long a,
                                     unsigned long long b) {
    asm("fma.rn.f32x2 %0, %1, %2, %0;" : "+l"(d) : "l"(a), "l"(b));
}

__device__ __forceinline__ float sigmoidf_(float x) {
    return 1.0f / (1.0f + expf(-x));
}

// ====================================================================
// Prep 1: pack [W_ih ; W_hh] -> g_W0pack[k][col], col = jt*96 + g*24 + jj
// ====================================================================
__global__ void prepW0(const float* __restrict__ Wih, const float* __restrict__ Whh) {
    const int stride = gridDim.x * blockDim.x;
    for (int idx = blockIdx.x * blockDim.x + threadIdx.x; idx < 1536 * 3072; idx += stride) {
        int k   = idx / 3072;
        int col = idx - k * 3072;
        int jt  = col / 96;
        int r   = col - jt * 96;
        int g   = r / 24;
        int jj  = r - g * 24;
        int row = g * HID + jt * 24 + jj; // row in the 4H x H weight
        float v = (k < HID) ? Wih[row * HID + k] : Whh[row * HID + (k - HID)];
        g_W0pack[idx] = v;
    }
}

// ====================================================================
// Prep 2: Wcomb pack (from W0pack, coalesced), A0, C init, packed bias
// ====================================================================
__global__ void prepRest(const float* __restrict__ src, const float* __restrict__ h0,
                         const float* __restrict__ c0, const float* __restrict__ bih,
                         const float* __restrict__ bhh) {
    const int stride = gridDim.x * blockDim.x;
    const int t0 = blockIdx.x * blockDim.x + threadIdx.x;

    // Wcomb[k][col] = W0pack[k][col] + W0pack[k+768][col]
    for (int idx = t0; idx < 768 * 3072; idx += stride)
        g_Wcpack[idx] = g_W0pack[idx] + g_W0pack[idx + 768 * 3072];

    // A0 = [x0 | h0], x0 = src[:, SRCL-1, :]
    for (int idx = t0; idx < BATCH * 1536; idx += stride) {
        int b = idx / 1536;
        int q = idx - b * 1536;
        g_A0[idx] = (q < HID) ? src[(b * SRCL + (SRCL - 1)) * HID + q]
                              : h0[b * HID + (q - HID)];
    }

    // C state init
    for (int idx = t0; idx < BATCH * HID; idx += stride)
        g_C[idx] = c0[idx];

    // packed fused bias: biasP[col] = bih[row(col)] + bhh[row(col)]
    for (int idx = t0; idx < G4; idx += stride) {
        int jt = idx / 96;
        int r  = idx - jt * 96;
        int g  = r / 24;
        int jj = r - g * 24;
        int row = g * HID + jt * 24 + jj;
        g_biasP[idx] = bih[row] + bhh[row];
    }
}

// ====================================================================
// LSTM step: gates GEMM (M=256, Npacked=3072, K=768 or 1536) + pointwise
// grid (32 jt, 8 mt), 256 threads. CTA gate tile: 32 m x (24 j x 4 gates).
// -> 256 CTAs = 2 CTAs/SM so one CTA's barriers hide behind the other's
//    compute (R6 showed 1 CTA/SM leaves fma at 32% with all-bubble gaps).
// Per-thread: 2 m (tm) x 3 col-pairs (tc) = 6 f32x2 accumulators.
// A staged in smem PRE-DUPLICATED (float2(x,x)); double-buffered smem,
// CH=32 -> one __syncthreads per 32-k chunk (24 barriers per step).
// Alignment: Ad inner dim 34 (even) -> row stride 272B (16B multiple) so
// the ulonglong2 LDS.128 reads stay aligned for every k.
// ====================================================================
__global__ __launch_bounds__(256) void lstm_step(int t) {
    __shared__ __align__(16) union SM {
        struct {
            float2 Ad[2][CH][34];   // [buf][k][m] duplicated A rows (32 used, pad 34)
            float  W [2][CH][96];   // [buf][k][packed col]
        } p;
        float G[32][96];            // gate tile for pointwise (reused after GEMM)
    } sm;

    const float* A;
    int lda, kTot;
    if (t == 0) { A = g_A0; lda = 1536; kTot = 1536; }
    else        { A = g_H + (size_t)(t - 1) * BH; lda = HID; kTot = HID; }
    const float* __restrict__ Wp = (t == 0) ? g_W0pack : g_Wcpack;
    float* __restrict__ hOut = g_H + (size_t)t * BH;

    const int tid = threadIdx.x;
    const int jt  = blockIdx.x;
    const int m0  = blockIdx.y * 32;
    const int tm  = tid >> 4;         // 0..15  -> m rows 2*tm, 2*tm+1
    const int tc  = tid & 15;         // 0..15  -> cols tc*6..tc*6+5
    const int lr  = tid >> 3;         // 0..31  A-load row
    const int lk  = (tid & 7) * 4;    // A-load k offset (float4), 0..28

    const float* __restrict__ Wbase = Wp + jt * 96;

    // W-load coordinates: 32k x 48 float2-slots = 1536 slots / 256 thr = 6 each
    int wk[6], wc2[6];
#pragma unroll
    for (int l = 0; l < 6; l++) {
        int lin = tid + 256 * l;
        wk[l]  = lin / 48;
        wc2[l] = lin - wk[l] * 48;
    }

    // accumulators initialized with packed bias (folds bias add into GEMM)
    unsigned long long acc[2][3];
    {
        const float* bP = g_biasP + jt * 96 + tc * 6;
        unsigned long long b0 = *(const unsigned long long*)(bP + 0);
        unsigned long long b1 = *(const unsigned long long*)(bP + 2);
        unsigned long long b2 = *(const unsigned long long*)(bP + 4);
#pragma unroll
        for (int mi = 0; mi < 2; mi++) {
            acc[mi][0] = b0; acc[mi][1] = b1; acc[mi][2] = b2;
        }
    }

    const int nCh = kTot / CH;
    const float* aPtr = A + (size_t)(m0 + lr) * lda;

    // prefetch chunk 0
    float4 aR = *(const float4*)(aPtr + lk);
    float2 wR[6];
#pragma unroll
    for (int l = 0; l < 6; l++)
        wR[l] = *(const float2*)(Wbase + (size_t)wk[l] * G4 + wc2[l] * 2);

    // stage chunk 0 into buf 0
    sm.p.Ad[0][lk + 0][lr] = make_float2(aR.x, aR.x);
    sm.p.Ad[0][lk + 1][lr] = make_float2(aR.y, aR.y);
    sm.p.Ad[0][lk + 2][lr] = make_float2(aR.z, aR.z);
    sm.p.Ad[0][lk + 3][lr] = make_float2(aR.w, aR.w);
#pragma unroll
    for (int l = 0; l < 6; l++)
        *(float2*)&sm.p.W[0][wk[l]][wc2[l] * 2] = wR[l];
    __syncthreads();

    int buf = 0;
    for (int ch = 0; ch < nCh; ch++) {
        const bool more = (ch + 1 < nCh);
        // issue global prefetch for next chunk (latency overlapped by compute)
        if (more) {
            int kn = (ch + 1) * CH;
            aR = *(const float4*)(aPtr + kn + lk);
#pragma unroll
            for (int l = 0; l < 6; l++)
                wR[l] = *(const float2*)(Wbase + (size_t)(kn + wk[l]) * G4 + wc2[l] * 2);
        }

        // compute current chunk from buf: per k = 1 LDS.128 + 3 LDS.64 + 6 FFMA2
#pragma unroll
        for (int k = 0; k < CH; k++) {
            ulonglong2 Ap = *(const ulonglong2*)&sm.p.Ad[buf][k][tm * 2];
            unsigned long long w0 = *(const unsigned long long*)&sm.p.W[buf][k][tc * 6 + 0];
            unsigned long long w1 = *(const unsigned long long*)&sm.p.W[buf][k][tc * 6 + 2];
            unsigned long long w2 = *(const unsigned long long*)&sm.p.W[buf][k][tc * 6 + 4];
            fma2(acc[0][0], Ap.x, w0);
            fma2(acc[0][1], Ap.x, w1);
            fma2(acc[0][2], Ap.x, w2);
            fma2(acc[1][0], Ap.y, w0);
            fma2(acc[1][1], Ap.y, w1);
            fma2(acc[1][2], Ap.y, w2);
        }

        // stage next chunk into other buffer (globals have landed by now)
        if (more) {
            int nb = buf ^ 1;
            sm.p.Ad[nb][lk + 0][lr] = make_float2(aR.x, aR.x);
            sm.p.Ad[nb][lk + 1][lr] = make_float2(aR.y, aR.y);
            sm.p.Ad[nb][lk + 2][lr] = make_float2(aR.z, aR.z);
            sm.p.Ad[nb][lk + 3][lr] = make_float2(aR.w, aR.w);
#pragma unroll
            for (int l = 0; l < 6; l++)
                *(float2*)&sm.p.W[nb][wk[l]][wc2[l] * 2] = wR[l];
        }
        __syncthreads();     // one barrier per chunk
        buf ^= 1;
    }

    // gates (with bias) -> smem for pointwise regrouping (union reuse: safe,
    // last compute-read of p.* happens before the loop's final barrier)
#pragma unroll
    for (int mi = 0; mi < 2; mi++)
#pragma unroll
        for (int wi = 0; wi < 3; wi++)
            *(unsigned long long*)&sm.G[tm * 2 + mi][tc * 6 + 2 * wi] = acc[mi][wi];
    __syncthreads();

    // fused LSTM pointwise: 32 m x 24 j = 768 elems / 256 threads = 3 each
#pragma unroll
    for (int e = 0; e < 3; e++) {
        int lin = e * 256 + tid;
        int m  = lin / 24;
        int jj = lin - m * 24;
        int gj = jt * 24 + jj;          // global hidden index
        int b  = m0 + m;
        float gi = sm.G[m][jj];
        float gf = sm.G[m][24 + jj];
        float gg = sm.G[m][48 + jj];
        float go = sm.G[m][72 + jj];
        float si = sigmoidf_(gi);
        float sf = sigmoidf_(gf);
        float so = sigmoidf_(go);
        float tg = tanhf(gg);
        int ci = b * HID + gj;
        float c = sf * g_C[ci] + si * tg;
        g_C[ci]  = c;
        hOut[ci] = so * tanhf(c);
    }
}

// ====================================================================
// Post projection: out[b][t][o] = H[t][b][:] . W_post[o][:] + b_post[o]
// grid (100 t, 4 mt), 128 threads. Thread tile: 2 m x 18 o (f32x2 over o-pairs).
// ====================================================================
__global__ __launch_bounds__(128) void post_proj(const float* __restrict__ Wpost,
                                                 const float* __restrict__ bpost,
                                                 float* __restrict__ out) {
    __shared__ float pA[16][64];  // [k][m]
    __shared__ float pW[16][72];  // [k][o]

    const int tid = threadIdx.x;
    const int t   = blockIdx.x;
    const int m0  = blockIdx.y * 64;
    const int tm  = tid >> 2;          // 0..31 -> m = 2*tm
    const int to  = tid & 3;           // 0..3  -> o base = 18*to
    const int m   = 2 * tm;
    const int ob  = 18 * to;

    const int lr = tid >> 1;           // 0..63 A-load row
    const int lk = (tid & 1) * 8;      // A-load k offset (two float4)

    const float* __restrict__ Abase = g_H + (size_t)t * BH + (size_t)m0 * HID;

    unsigned long long acc[2][9];
#pragma unroll
    for (int mi = 0; mi < 2; mi++)
#pragma unroll
        for (int oi = 0; oi < 9; oi++) acc[mi][oi] = 0ull;

    for (int kc = 0; kc < HID; kc += 16) {
        // load A tile: 16k x 64m = 1024 floats / 128 thr = 8 each
        float4 v0 = *(const float4*)&Abase[(size_t)lr * HID + kc + lk];
        float4 v1 = *(const float4*)&Abase[(size_t)lr * HID + kc + lk + 4];
        pA[lk + 0][lr] = v0.x; pA[lk + 1][lr] = v0.y;
        pA[lk + 2][lr] = v0.z; pA[lk + 3][lr] = v0.w;
        pA[lk + 4][lr] = v1.x; pA[lk + 5][lr] = v1.y;
        pA[lk + 6][lr] = v1.z; pA[lk + 7][lr] = v1.w;
        // load W tile: 16k x 72o = 1152 / 128 = 9 each
#pragma unroll
        for (int l = 0; l < 9; l++) {
            int lin = tid + 128 * l;
            int k = lin / 72;
            int o = lin - k * 72;
            pW[k][o] = Wpost[o * HID + kc + k];
        }
        __syncthreads();

#pragma unroll
        for (int k = 0; k < 16; k++) {
            float2 av = *(const float2*)&pA[k][m];
            unsigned long long a0 = pack2(av.x, av.x);
            unsigned long long a1 = pack2(av.y, av.y);
#pragma unroll
            for (int oi = 0; oi < 9; oi++) {
                unsigned long long w = *(const unsigned long long*)&pW[k][ob + 2 * oi];
                fma2(acc[0][oi], a0, w);
                fma2(acc[1][oi], a1, w);
            }
        }
        __syncthreads();
    }

#pragma unroll
    for (int mi = 0; mi < 2; mi++) {
        int b = m0 + m + mi;
        float* orow = out + (size_t)b * (TLEN * OUTD) + t * OUTD;
#pragma unroll
        for (int oi = 0; oi < 9; oi++) {
            float x, y;
            unpack2(acc[mi][oi], x, y);
            int o = ob + 2 * oi;
            orow[o]     = x + bpost[o];
            orow[o + 1] = y + bpost[o + 1];
        }
    }
}

// ====================================================================
// kernel_launch: prep -> 100 sequential LSTM steps -> projection
// (graph-capturable: kernel launches only, no allocs/syncs)
// ====================================================================
extern "C" void kernel_launch(void* const* d_in, const int* in_sizes, int n_in,
                              void* d_out, int out_size) {
    const float* src   = (const float*)d_in[0];
    // d_in[1] = tgt (only its length T matters; unused at runtime)
    const float* h0    = (const float*)d_in[2];
    const float* c0    = (const float*)d_in[3];
    const float* Wih   = (const float*)d_in[4];
    const float* Whh   = (const float*)d_in[5];
    const float* bih   = (const float*)d_in[6];
    const float* bhh   = (const float*)d_in[7];
    const float* Wpost = (const float*)d_in[8];
    const float* bpost = (const float*)d_in[9];
    float* out = (float*)d_out;

    prepW0<<<2048, 256>>>(Wih, Whh);
    prepRest<<<2048, 256>>>(src, h0, c0, bih, bhh);

    dim3 sgrid(32, 8);   // 256 CTAs: 32 col-tiles x 8 m-tiles -> 2 CTAs/SM
    for (int t = 0; t < TLEN; t++)
        lstm_step<<<sgrid, 256>>>(t);

    dim3 pgrid(TLEN, 4);
    post_proj<<<pgrid, 128>>>(Wpost, bpost, out);
}

// round 10
// speedup vs baseline: 1.6105x; 1.6105x over previous
#include <cuda_runtime.h>
#include <cuda_fp16.h>
#include <math.h>
#include <stdint.h>

// Problem constants
#define BATCH 256
#define HID   768
#define G4    3072
#define TLEN  100
#define OUTD  72
#define SRCL  16
#define BH    (BATCH * HID)

// step-kernel geometry (mma.sync path, base sm_103 target — no tcgen05)
#define STAGE_K   64                  // k per smem stage: 64 fp16 = 128B row
#define TILEB     16384               // 128 rows x 128B
#define BUFB      (2 * TILEB)         // A tile + W tile per stage
#define GSTRIDE   132                 // gate smem row stride (f32)
#define DYN_SMEM  (1024 + 128 * GSTRIDE * 4)  // >= 1024 + max(2*BUFB=65536, G=67584)

// -------- device scratch (allocation-free: __device__ globals) --------
static __device__ __half g_Wr [G4 * 1536];      // rec W (Wih+Whh): row n -> [wh(768)|wl(768)]
static __device__ __half g_W0 [G4 * 3072];      // t=0 W [Wih|Whh]: row n -> [w0h(1536)|w0l(1536)]
static __device__ __half g_A0b[BATCH * 3072];   // [a0h(1536)|a0l(1536)], a0=[x0|h0]
static __device__ __half g_Ab [2][BATCH * 1536];// h hi/lo ping-pong: row m -> [hh(768)|hl(768)]
static __device__ float g_C[BATCH * HID];       // cell state
static __device__ float g_H[TLEN * BATCH * HID];// fp32 h history (post_proj input)
static __device__ float g_biasPk[G4];           // bias in packed-N layout: n = nt*128 + g*32 + jj

// -------- helpers --------
__device__ __forceinline__ uint32_t smem_u32(const void* p) {
    uint32_t a;
    asm("{ .reg .u64 t; cvta.to.shared.u64 t, %1; cvt.u32.u64 %0, t; }" : "=r"(a) : "l"(p));
    return a;
}
#define SWZ128(o) ((o) ^ (((o) >> 3) & 0x70))

__device__ __forceinline__ float sigmoidf_(float x) { return 1.0f / (1.0f + expf(-x)); }

__device__ __forceinline__ void cp_async16(uint32_t dst, const void* src) {
    asm volatile("cp.async.cg.shared.global [%0], [%1], 16;" :: "r"(dst), "l"(src));
}
#define CP_COMMIT()  asm volatile("cp.async.commit_group;" ::: "memory")
#define CP_WAIT(n)   asm volatile("cp.async.wait_group %0;" :: "n"(n) : "memory")

__device__ __forceinline__ void ldsm4(uint32_t* r, uint32_t addr) {
    asm volatile("ldmatrix.sync.aligned.m8n8.x4.shared.b16 {%0,%1,%2,%3}, [%4];"
                 : "=r"(r[0]), "=r"(r[1]), "=r"(r[2]), "=r"(r[3]) : "r"(addr));
}
__device__ __forceinline__ void mma16816(float* c, const uint32_t* a, const uint32_t* b) {
    asm volatile("mma.sync.aligned.m16n8k16.row.col.f32.f16.f16.f32 "
                 "{%0,%1,%2,%3}, {%4,%5,%6,%7}, {%8,%9}, {%0,%1,%2,%3};"
                 : "+f"(c[0]), "+f"(c[1]), "+f"(c[2]), "+f"(c[3])
                 : "r"(a[0]), "r"(a[1]), "r"(a[2]), "r"(a[3]), "r"(b[0]), "r"(b[1]));
}

// f32x2 helpers (post_proj)
__device__ __forceinline__ unsigned long long pack2(float x, float y) {
    unsigned long long r; asm("mov.b64 %0, {%1, %2};" : "=l"(r) : "f"(x), "f"(y)); return r;
}
__device__ __forceinline__ void unpack2(unsigned long long v, float& x, float& y) {
    asm("mov.b64 {%0, %1}, %2;" : "=f"(x), "=f"(y) : "l"(v));
}
__device__ __forceinline__ void fma2(unsigned long long& d, unsigned long long a, unsigned long long b) {
    asm("fma.rn.f32x2 %0, %1, %2, %0;" : "+l"(d) : "l"(a), "l"(b));
}

// row in original 4H x H weight from packed-N index n (n = nt*128 + g*32 + jj)
__device__ __forceinline__ int rowFromN(int n) {
    int nt = n >> 7, r = n & 127, g = r >> 5, jj = r & 31;
    return g * HID + nt * 32 + jj;
}

// ====================================================================
// Prep kernels: fp16 hi/lo packing of weights and initial state
// ====================================================================
__global__ void prepWr(const float* __restrict__ Wih, const float* __restrict__ Whh) {
    const int stride = gridDim.x * blockDim.x;
    for (int idx = blockIdx.x * blockDim.x + threadIdx.x; idx < G4 * HID; idx += stride) {
        int n = idx / HID, k = idx - n * HID;
        int row = rowFromN(n);
        float w = Wih[row * HID + k] + Whh[row * HID + k];
        __half wh = __float2half_rn(w);
        g_Wr[n * 1536 + k]       = wh;
        g_Wr[n * 1536 + 768 + k] = __float2half_rn(w - __half2float(wh));
    }
}
__global__ void prepW0k(const float* __restrict__ Wih, const float* __restrict__ Whh) {
    const int stride = gridDim.x * blockDim.x;
    for (int idx = blockIdx.x * blockDim.x + threadIdx.x; idx < G4 * 1536; idx += stride) {
        int n = idx / 1536, k = idx - n * 1536;
        int row = rowFromN(n);
        float w = (k < HID) ? Wih[row * HID + k] : Whh[row * HID + (k - HID)];
        __half wh = __float2half_rn(w);
        g_W0[n * 3072 + k]        = wh;
        g_W0[n * 3072 + 1536 + k] = __float2half_rn(w - __half2float(wh));
    }
}
__global__ void prepState(const float* __restrict__ src, const float* __restrict__ h0,
                          const float* __restrict__ c0, const float* __restrict__ bih,
                          const float* __restrict__ bhh) {
    const int stride = gridDim.x * blockDim.x;
    const int t0 = blockIdx.x * blockDim.x + threadIdx.x;
    for (int idx = t0; idx < BATCH * 1536; idx += stride) {
        int m = idx / 1536, q = idx - m * 1536;
        float a = (q < HID) ? src[(m * SRCL + (SRCL - 1)) * HID + q] : h0[m * HID + (q - HID)];
        __half ah = __float2half_rn(a);
        g_A0b[m * 3072 + q]        = ah;
        g_A0b[m * 3072 + 1536 + q] = __float2half_rn(a - __half2float(ah));
    }
    for (int idx = t0; idx < BATCH * HID; idx += stride) g_C[idx] = c0[idx];
    for (int idx = t0; idx < G4; idx += stride) {
        int row = rowFromN(idx);
        g_biasPk[idx] = bih[row] + bhh[row];
    }
}

// ====================================================================
// LSTM step via mma.sync (HMMA). Grid (24 nt, 2 mt), 256 thr (8 warps).
// CTA tile 128m x 128n; warp tile 64m x 32n; K_eff = 3*kBase fp16-split.
// cp.async double-buffered 64-k stages, SW128 swizzle, ldmatrix frags.
// Epilogue: gates -> smem -> fused LSTM pointwise; h out fp32 + fp16 hi/lo.
// ====================================================================
__global__ __launch_bounds__(256) void lstm_step_mma(int t) {
    extern __shared__ char dyn_raw[];
    char* smb = (char*)(((uintptr_t)dyn_raw + 1023) & ~(uintptr_t)1023);

    const int tid  = threadIdx.x;
    const int wid  = tid >> 5;
    const int lane = tid & 31;
    const int nt   = blockIdx.x;
    const int m0   = blockIdx.y * 128;
    const int n0   = nt * 128;

    const __half* Aglob; const __half* Wglob; int kBase;
    if (t == 0) { Aglob = g_A0b; Wglob = g_W0; kBase = 1536; }
    else        { Aglob = g_Ab[t & 1]; Wglob = g_Wr; kBase = 768; }
    const int rowStride = 2 * kBase;
    const int nStages   = (3 * kBase) / STAGE_K;

    // warp tiling: mw in {0,1} (64m), nw in {0..3} (32n)
    const int mwOff = (wid & 1) * 64;
    const int nwOff = (wid >> 1) * 32;

    // fill coords: 4 chunks of (row = l>>3, cb = (l&7)*16) per tile
    const int frow = tid >> 3;          // 0..31, +32 per chunk
    const int fcb  = (tid & 7) * 16;

    // ldmatrix per-lane coords
    const int grp = lane >> 3, lrw = lane & 7;
    const int aRow = ((grp & 1) ? 8 : 0) + lrw;      // + mf*16 + mwOff
    const int aKx  = (grp & 2) ? 16 : 0;
    const int bRow = ((grp & 2) ? 8 : 0) + lrw;      // + nf16 + nwOff
    const int bKx  = (grp & 1) ? 16 : 0;

    const uint32_t smb32 = smem_u32(smb);

    float acc[4][4][4];                 // [mf][n8][c]
#pragma unroll
    for (int a = 0; a < 4; a++)
#pragma unroll
        for (int b = 0; b < 4; b++)
#pragma unroll
            for (int c = 0; c < 4; c++) acc[a][b][c] = 0.0f;

    // stage filler: cp.async 8x16B per thread into buf (s&1)
    auto fill = [&](int s) {
        const int b = s & 1;
        const uint32_t dA = smb32 + b * BUFB;
        const uint32_t dW = dA + TILEB;
        const int segBase = s * STAGE_K;
        const int seg = segBase / kBase;
        const int kk  = segBase - seg * kBase;
        const int aOff = (seg == 1) ? kBase + kk : kk;   // [ah*wh | al*wh | ah*wl]
        const int wOff = (seg == 2) ? kBase + kk : kk;
#pragma unroll
        for (int i = 0; i < 4; i++) {
            int row = frow + 32 * i;
            cp_async16(dA + SWZ128(row * 128 + fcb),
                       (const char*)Aglob + ((size_t)(m0 + row) * rowStride + aOff) * 2 + fcb);
        }
#pragma unroll
        for (int i = 0; i < 4; i++) {
            int row = frow + 32 * i;
            cp_async16(dW + SWZ128(row * 128 + fcb),
                       (const char*)Wglob + ((size_t)(n0 + row) * rowStride + wOff) * 2 + fcb);
        }
    };

    fill(0); CP_COMMIT();

    for (int s = 0; s < nStages; s++) {
        if (s + 1 < nStages) { fill(s + 1); CP_COMMIT(); CP_WAIT(1); }
        else                 { CP_WAIT(0); }
        __syncthreads();

        const uint32_t bA = smb32 + (s & 1) * BUFB;
        const uint32_t bW = bA + TILEB;
#pragma unroll
        for (int k16 = 0; k16 < 4; k16++) {
            const int kb = k16 * 32;     // bytes into 128B row
            uint32_t af[4][4];
#pragma unroll
            for (int mf = 0; mf < 4; mf++) {
                int row = mwOff + mf * 16 + aRow;
                ldsm4(af[mf], bA + SWZ128(row * 128 + kb + aKx));
            }
            uint32_t bf[2][4];
#pragma unroll
            for (int nf = 0; nf < 2; nf++) {
                int row = nwOff + nf * 16 + bRow;
                ldsm4(bf[nf], bW + SWZ128(row * 128 + kb + bKx));
            }
#pragma unroll
            for (int mf = 0; mf < 4; mf++) {
                mma16816(acc[mf][0], af[mf], &bf[0][0]);
                mma16816(acc[mf][1], af[mf], &bf[0][2]);
                mma16816(acc[mf][2], af[mf], &bf[1][0]);
                mma16816(acc[mf][3], af[mf], &bf[1][2]);
            }
        }
        __syncthreads();
    }

    // gates -> smem (reuse pipeline smem; all compute done)
    float* G = (float*)smb;
    {
        const int r0 = lane >> 2, c0 = 2 * (lane & 3);
#pragma unroll
        for (int mf = 0; mf < 4; mf++) {
#pragma unroll
            for (int n8 = 0; n8 < 4; n8++) {
                int row = mwOff + mf * 16 + r0;
                int col = nwOff + n8 * 8 + c0;
                *(float2*)&G[row * GSTRIDE + col]       = make_float2(acc[mf][n8][0], acc[mf][n8][1]);
                *(float2*)&G[(row + 8) * GSTRIDE + col] = make_float2(acc[mf][n8][2], acc[mf][n8][3]);
            }
        }
    }
    __syncthreads();

    // fused LSTM pointwise: 128m x 32j = 4096 cells / 256 thr = 16 each
    const float* bias = g_biasPk + n0;
    float* Hbase = g_H + (size_t)t * BH;
    __half* AbN = g_Ab[(t + 1) & 1];
#pragma unroll
    for (int e = 0; e < 16; e++) {
        int cell = e * 256 + tid;
        int m  = cell >> 5;             // 0..127
        int jj = cell & 31;
        int b  = m0 + m;
        int gj = nt * 32 + jj;
        float gi = G[m * GSTRIDE + jj]      + bias[jj];
        float gf = G[m * GSTRIDE + 32 + jj] + bias[32 + jj];
        float gg = G[m * GSTRIDE + 64 + jj] + bias[64 + jj];
        float go = G[m * GSTRIDE + 96 + jj] + bias[96 + jj];
        int ci = b * HID + gj;
        float c = sigmoidf_(gf) * g_C[ci] + sigmoidf_(gi) * tanhf(gg);
        g_C[ci] = c;
        float h = sigmoidf_(go) * tanhf(c);
        Hbase[ci] = h;
        __half hh = __float2half_rn(h);
        AbN[(size_t)b * 1536 + gj]       = hh;
        AbN[(size_t)b * 1536 + 768 + gj] = __float2half_rn(h - __half2float(hh));
    }
}

// ====================================================================
// Post projection: out[b][t][o] = H[t][b][:] . W_post[o][:] + b_post[o]
// grid (100 t, 4 mt), 128 threads. Thread tile: 2 m x 18 o (f32x2).
// ====================================================================
__global__ __launch_bounds__(128) void post_proj(const float* __restrict__ Wpost,
                                                 const float* __restrict__ bpost,
                                                 float* __restrict__ out) {
    __shared__ float pA[16][64];
    __shared__ float pW[16][72];

    const int tid = threadIdx.x;
    const int t   = blockIdx.x;
    const int m0  = blockIdx.y * 64;
    const int tm  = tid >> 2;
    const int to  = tid & 3;
    const int m   = 2 * tm;
    const int ob  = 18 * to;
    const int lr  = tid >> 1;
    const int lk  = (tid & 1) * 8;

    const float* __restrict__ Abase = g_H + (size_t)t * BH + (size_t)m0 * HID;

    unsigned long long acc[2][9];
#pragma unroll
    for (int mi = 0; mi < 2; mi++)
#pragma unroll
        for (int oi = 0; oi < 9; oi++) acc[mi][oi] = 0ull;

    for (int kc = 0; kc < HID; kc += 16) {
        float4 v0 = *(const float4*)&Abase[(size_t)lr * HID + kc + lk];
        float4 v1 = *(const float4*)&Abase[(size_t)lr * HID + kc + lk + 4];
        pA[lk + 0][lr] = v0.x; pA[lk + 1][lr] = v0.y;
        pA[lk + 2][lr] = v0.z; pA[lk + 3][lr] = v0.w;
        pA[lk + 4][lr] = v1.x; pA[lk + 5][lr] = v1.y;
        pA[lk + 6][lr] = v1.z; pA[lk + 7][lr] = v1.w;
#pragma unroll
        for (int l = 0; l < 9; l++) {
            int lin = tid + 128 * l;
            int k = lin / 72;
            int o = lin - k * 72;
            pW[k][o] = Wpost[o * HID + kc + k];
        }
        __syncthreads();
#pragma unroll
        for (int k = 0; k < 16; k++) {
            float2 av = *(const float2*)&pA[k][m];
            unsigned long long a0 = pack2(av.x, av.x);
            unsigned long long a1 = pack2(av.y, av.y);
#pragma unroll
            for (int oi = 0; oi < 9; oi++) {
                unsigned long long w = *(const unsigned long long*)&pW[k][ob + 2 * oi];
                fma2(acc[0][oi], a0, w);
                fma2(acc[1][oi], a1, w);
            }
        }
        __syncthreads();
    }
#pragma unroll
    for (int mi = 0; mi < 2; mi++) {
        int b = m0 + m + mi;
        float* orow = out + (size_t)b * (TLEN * OUTD) + t * OUTD;
#pragma unroll
        for (int oi = 0; oi < 9; oi++) {
            float x, y;
            unpack2(acc[mi][oi], x, y);
            int o = ob + 2 * oi;
            orow[o]     = x + bpost[o];
            orow[o + 1] = y + bpost[o + 1];
        }
    }
}

// ====================================================================
// kernel_launch
// ====================================================================
extern "C" void kernel_launch(void* const* d_in, const int* in_sizes, int n_in,
                              void* d_out, int out_size) {
    const float* src   = (const float*)d_in[0];
    const float* h0    = (const float*)d_in[2];
    const float* c0    = (const float*)d_in[3];
    const float* Wih   = (const float*)d_in[4];
    const float* Whh   = (const float*)d_in[5];
    const float* bih   = (const float*)d_in[6];
    const float* bhh   = (const float*)d_in[7];
    const float* Wpost = (const float*)d_in[8];
    const float* bpost = (const float*)d_in[9];
    float* out = (float*)d_out;

    cudaFuncSetAttribute(lstm_step_mma, cudaFuncAttributeMaxDynamicSharedMemorySize, DYN_SMEM);

    prepWr   <<<2048, 256>>>(Wih, Whh);
    prepW0k  <<<2048, 256>>>(Wih, Whh);
    prepState<<<2048, 256>>>(src, h0, c0, bih, bhh);

    dim3 sgrid(24, 2);     // 24 N-tiles (128 packed gate cols) x 2 M-tiles (128 batch)
    for (int t = 0; t < TLEN; t++)
        lstm_step_mma<<<sgrid, 256, DYN_SMEM>>>(t);

    dim3 pgrid(TLEN, 4);
    post_proj<<<pgrid, 128>>>(Wpost, bpost, out);
}

// round 11
// speedup vs baseline: 2.3344x; 1.4495x over previous
#include <cuda_runtime.h>
#include <cuda_fp16.h>
#include <math.h>
#include <stdint.h>

// Problem constants
#define BATCH 256
#define HID   768
#define G4    3072
#define TLEN  100
#define OUTD  72
#define SRCL  16
#define BH    (BATCH * HID)

// step-kernel geometry (mma.sync path, base sm_103 target — no tcgen05)
// Gate packing: n = j*4 + g  (4-gate quadruple adjacent -> any N tile mult of 4)
#define STAGE_K   64                  // k per smem stage: 64 fp16 = 128B row
#define A_TILEB   16384               // 128 m-rows x 128B
#define W_TILEB   8192                // 64 n-rows x 128B
#define BUFB      (A_TILEB + W_TILEB) // 24KB per stage
#define GSTRIDE   68                  // gate smem row stride (f32), 68*4=272B (16B mult)
#define DYN_SMEM  (1024 + 2 * BUFB)   // 49KB pipeline; G tile (128*68*4=34.8KB) fits under

// -------- device scratch (allocation-free: __device__ globals) --------
static __device__ __half g_Wr [G4 * 1536];      // rec W (Wih+Whh): row n -> [wh(768)|wl(768)]
static __device__ __half g_W0 [G4 * 3072];      // t=0 W [Wih|Whh]: row n -> [w0h(1536)|w0l(1536)]
static __device__ __half g_A0b[BATCH * 3072];   // [a0h(1536)|a0l(1536)], a0=[x0|h0]
static __device__ __half g_Ab [2][BATCH * 1536];// h hi/lo ping-pong: row m -> [hh(768)|hl(768)]
static __device__ float g_C[BATCH * HID];       // cell state
static __device__ float g_H[TLEN * BATCH * HID];// fp32 h history (post_proj input)
static __device__ float g_biasPk[G4];           // bias in packed-N layout: n = j*4 + g

// -------- helpers --------
__device__ __forceinline__ uint32_t smem_u32(const void* p) {
    uint32_t a;
    asm("{ .reg .u64 t; cvta.to.shared.u64 t, %1; cvt.u32.u64 %0, t; }" : "=r"(a) : "l"(p));
    return a;
}
#define SWZ128(o) ((o) ^ (((o) >> 3) & 0x70))

__device__ __forceinline__ float sigmoidf_(float x) { return 1.0f / (1.0f + expf(-x)); }

__device__ __forceinline__ void cp_async16(uint32_t dst, const void* src) {
    asm volatile("cp.async.cg.shared.global [%0], [%1], 16;" :: "r"(dst), "l"(src));
}
#define CP_COMMIT()  asm volatile("cp.async.commit_group;" ::: "memory")
#define CP_WAIT(n)   asm volatile("cp.async.wait_group %0;" :: "n"(n) : "memory")

__device__ __forceinline__ void ldsm4(uint32_t* r, uint32_t addr) {
    asm volatile("ldmatrix.sync.aligned.m8n8.x4.shared.b16 {%0,%1,%2,%3}, [%4];"
                 : "=r"(r[0]), "=r"(r[1]), "=r"(r[2]), "=r"(r[3]) : "r"(addr));
}
__device__ __forceinline__ void mma16816(float* c, const uint32_t* a, const uint32_t* b) {
    asm volatile("mma.sync.aligned.m16n8k16.row.col.f32.f16.f16.f32 "
                 "{%0,%1,%2,%3}, {%4,%5,%6,%7}, {%8,%9}, {%0,%1,%2,%3};"
                 : "+f"(c[0]), "+f"(c[1]), "+f"(c[2]), "+f"(c[3])
                 : "r"(a[0]), "r"(a[1]), "r"(a[2]), "r"(a[3]), "r"(b[0]), "r"(b[1]));
}

// f32x2 helpers (post_proj)
__device__ __forceinline__ unsigned long long pack2(float x, float y) {
    unsigned long long r; asm("mov.b64 %0, {%1, %2};" : "=l"(r) : "f"(x), "f"(y)); return r;
}
__device__ __forceinline__ void unpack2(unsigned long long v, float& x, float& y) {
    asm("mov.b64 {%0, %1}, %2;" : "=f"(x), "=f"(y) : "l"(v));
}
__device__ __forceinline__ void fma2(unsigned long long& d, unsigned long long a, unsigned long long b) {
    asm("fma.rn.f32x2 %0, %1, %2, %0;" : "+l"(d) : "l"(a), "l"(b));
}

// original 4H x H weight row from packed-N index: n = j*4 + g -> row = g*768 + j
__device__ __forceinline__ int rowFromN(int n) {
    return (n & 3) * HID + (n >> 2);
}

// ====================================================================
// Prep kernels: fp16 hi/lo packing of weights and initial state
// ====================================================================
__global__ void prepWr(const float* __restrict__ Wih, const float* __restrict__ Whh) {
    const int stride = gridDim.x * blockDim.x;
    for (int idx = blockIdx.x * blockDim.x + threadIdx.x; idx < G4 * HID; idx += stride) {
        int n = idx / HID, k = idx - n * HID;
        int row = rowFromN(n);
        float w = Wih[row * HID + k] + Whh[row * HID + k];
        __half wh = __float2half_rn(w);
        g_Wr[n * 1536 + k]       = wh;
        g_Wr[n * 1536 + 768 + k] = __float2half_rn(w - __half2float(wh));
    }
}
__global__ void prepW0k(const float* __restrict__ Wih, const float* __restrict__ Whh) {
    const int stride = gridDim.x * blockDim.x;
    for (int idx = blockIdx.x * blockDim.x + threadIdx.x; idx < G4 * 1536; idx += stride) {
        int n = idx / 1536, k = idx - n * 1536;
        int row = rowFromN(n);
        float w = (k < HID) ? Wih[row * HID + k] : Whh[row * HID + (k - HID)];
        __half wh = __float2half_rn(w);
        g_W0[n * 3072 + k]        = wh;
        g_W0[n * 3072 + 1536 + k] = __float2half_rn(w - __half2float(wh));
    }
}
__global__ void prepState(const float* __restrict__ src, const float* __restrict__ h0,
                          const float* __restrict__ c0, const float* __restrict__ bih,
                          const float* __restrict__ bhh) {
    const int stride = gridDim.x * blockDim.x;
    const int t0 = blockIdx.x * blockDim.x + threadIdx.x;
    for (int idx = t0; idx < BATCH * 1536; idx += stride) {
        int m = idx / 1536, q = idx - m * 1536;
        float a = (q < HID) ? src[(m * SRCL + (SRCL - 1)) * HID + q] : h0[m * HID + (q - HID)];
        __half ah = __float2half_rn(a);
        g_A0b[m * 3072 + q]        = ah;
        g_A0b[m * 3072 + 1536 + q] = __float2half_rn(a - __half2float(ah));
    }
    for (int idx = t0; idx < BATCH * HID; idx += stride) g_C[idx] = c0[idx];
    for (int idx = t0; idx < G4; idx += stride) {
        int row = rowFromN(idx);
        g_biasPk[idx] = bih[row] + bhh[row];
    }
}

// ====================================================================
// LSTM step via mma.sync. Grid (48 nt, 2 mt) = 96 CTAs, 256 thr (8 warps).
// CTA tile 128m x 64n (16 hidden units x 4 gates); warp tile 32m x 32n.
// K_eff = 3*kBase fp16-split; cp.async double-buffered 64-k stages.
// Epilogue: gates -> smem -> fused LSTM pointwise (float4 per quadruple).
// ====================================================================
__global__ __launch_bounds__(256) void lstm_step_mma(int t) {
    extern __shared__ char dyn_raw[];
    char* smb = (char*)(((uintptr_t)dyn_raw + 1023) & ~(uintptr_t)1023);

    const int tid  = threadIdx.x;
    const int wid  = tid >> 5;
    const int lane = tid & 31;
    const int nt   = blockIdx.x;
    const int m0   = blockIdx.y * 128;
    const int n0   = nt * 64;

    const __half* Aglob; const __half* Wglob; int kBase;
    if (t == 0) { Aglob = g_A0b; Wglob = g_W0; kBase = 1536; }
    else        { Aglob = g_Ab[t & 1]; Wglob = g_Wr; kBase = 768; }
    const int rowStride = 2 * kBase;
    const int nStages   = (3 * kBase) / STAGE_K;

    // warp tiling: mw in {0..3} (32m each), nw in {0,1} (32n each)
    const int mwOff = (wid & 3) * 32;
    const int nwOff = (wid >> 2) * 32;

    // fill coords
    const int frow = tid >> 3;          // 0..31 (+32 per chunk)
    const int fcb  = (tid & 7) * 16;

    // ldmatrix per-lane coords (identical frag mapping as validated R9 kernel)
    const int grp = lane >> 3, lrw = lane & 7;
    const int aRow = ((grp & 1) ? 8 : 0) + lrw;
    const int aKx  = (grp & 2) ? 16 : 0;
    const int bRow = ((grp & 2) ? 8 : 0) + lrw;
    const int bKx  = (grp & 1) ? 16 : 0;

    const uint32_t smb32 = smem_u32(smb);

    float acc[2][4][4];                 // [mf][n8][c]
#pragma unroll
    for (int a = 0; a < 2; a++)
#pragma unroll
        for (int b = 0; b < 4; b++)
#pragma unroll
            for (int c = 0; c < 4; c++) acc[a][b][c] = 0.0f;

    // stage filler: A 4x16B + W 2x16B cp.async per thread into buf (s&1)
    auto fill = [&](int s) {
        const int b = s & 1;
        const uint32_t dA = smb32 + b * BUFB;
        const uint32_t dW = dA + A_TILEB;
        const int segBase = s * STAGE_K;
        const int seg = segBase / kBase;
        const int kk  = segBase - seg * kBase;
        const int aOff = (seg == 1) ? kBase + kk : kk;   // [ah*wh | al*wh | ah*wl]
        const int wOff = (seg == 2) ? kBase + kk : kk;
#pragma unroll
        for (int i = 0; i < 4; i++) {
            int row = frow + 32 * i;    // 0..127
            cp_async16(dA + SWZ128(row * 128 + fcb),
                       (const char*)Aglob + ((size_t)(m0 + row) * rowStride + aOff) * 2 + fcb);
        }
#pragma unroll
        for (int i = 0; i < 2; i++) {
            int row = frow + 32 * i;    // 0..63
            cp_async16(dW + SWZ128(row * 128 + fcb),
                       (const char*)Wglob + ((size_t)(n0 + row) * rowStride + wOff) * 2 + fcb);
        }
    };

    fill(0); CP_COMMIT();

    for (int s = 0; s < nStages; s++) {
        if (s + 1 < nStages) { fill(s + 1); CP_COMMIT(); CP_WAIT(1); }
        else                 { CP_WAIT(0); }
        __syncthreads();

        const uint32_t bA = smb32 + (s & 1) * BUFB;
        const uint32_t bW = bA + A_TILEB;
#pragma unroll
        for (int k16 = 0; k16 < 4; k16++) {
            const int kb = k16 * 32;     // bytes into 128B row
            uint32_t af[2][4];
#pragma unroll
            for (int mf = 0; mf < 2; mf++) {
                int row = mwOff + mf * 16 + aRow;
                ldsm4(af[mf], bA + SWZ128(row * 128 + kb + aKx));
            }
            uint32_t bf[2][4];
#pragma unroll
            for (int nf = 0; nf < 2; nf++) {
                int row = nwOff + nf * 16 + bRow;
                ldsm4(bf[nf], bW + SWZ128(row * 128 + kb + bKx));
            }
#pragma unroll
            for (int mf = 0; mf < 2; mf++) {
                mma16816(acc[mf][0], af[mf], &bf[0][0]);
                mma16816(acc[mf][1], af[mf], &bf[0][2]);
                mma16816(acc[mf][2], af[mf], &bf[1][0]);
                mma16816(acc[mf][3], af[mf], &bf[1][2]);
            }
        }
        __syncthreads();
    }

    // gates -> smem (reuse pipeline smem; all compute done)
    float* G = (float*)smb;
    {
        const int r0 = lane >> 2, c0 = 2 * (lane & 3);
#pragma unroll
        for (int mf = 0; mf < 2; mf++) {
#pragma unroll
            for (int n8 = 0; n8 < 4; n8++) {
                int row = mwOff + mf * 16 + r0;
                int col = nwOff + n8 * 8 + c0;
                *(float2*)&G[row * GSTRIDE + col]       = make_float2(acc[mf][n8][0], acc[mf][n8][1]);
                *(float2*)&G[(row + 8) * GSTRIDE + col] = make_float2(acc[mf][n8][2], acc[mf][n8][3]);
            }
        }
    }
    __syncthreads();

    // fused LSTM pointwise: 128m x 16 units = 2048 cells / 256 thr = 8 each.
    // Gate quadruple (i,f,g,o) is G[m][u*4 .. u*4+3] -> one float4.
    const float* bias = g_biasPk + n0;
    float* Hbase = g_H + (size_t)t * BH;
    __half* AbN = g_Ab[(t + 1) & 1];
    const int j0 = nt * 16;            // global hidden-unit base
#pragma unroll
    for (int e = 0; e < 8; e++) {
        int cell = e * 256 + tid;
        int m  = cell >> 4;             // 0..127
        int u  = cell & 15;
        int b  = m0 + m;
        int gj = j0 + u;
        float4 gv = *(const float4*)&G[m * GSTRIDE + u * 4];
        float4 bv = *(const float4*)&bias[u * 4];
        float gi = gv.x + bv.x;
        float gf = gv.y + bv.y;
        float gg = gv.z + bv.z;
        float go = gv.w + bv.w;
        int ci = b * HID + gj;
        float c = sigmoidf_(gf) * g_C[ci] + sigmoidf_(gi) * tanhf(gg);
        g_C[ci] = c;
        float h = sigmoidf_(go) * tanhf(c);
        Hbase[ci] = h;
        __half hh = __float2half_rn(h);
        AbN[(size_t)b * 1536 + gj]       = hh;
        AbN[(size_t)b * 1536 + 768 + gj] = __float2half_rn(h - __half2float(hh));
    }
}

// ====================================================================
// Post projection: out[b][t][o] = H[t][b][:] . W_post[o][:] + b_post[o]
// grid (100 t, 4 mt), 128 threads. Thread tile: 2 m x 18 o (f32x2).
// ====================================================================
__global__ __launch_bounds__(128) void post_proj(const float* __restrict__ Wpost,
                                                 const float* __restrict__ bpost,
                                                 float* __restrict__ out) {
    __shared__ float pA[16][64];
    __shared__ float pW[16][72];

    const int tid = threadIdx.x;
    const int t   = blockIdx.x;
    const int m0  = blockIdx.y * 64;
    const int tm  = tid >> 2;
    const int to  = tid & 3;
    const int m   = 2 * tm;
    const int ob  = 18 * to;
    const int lr  = tid >> 1;
    const int lk  = (tid & 1) * 8;

    const float* __restrict__ Abase = g_H + (size_t)t * BH + (size_t)m0 * HID;

    unsigned long long acc[2][9];
#pragma unroll
    for (int mi = 0; mi < 2; mi++)
#pragma unroll
        for (int oi = 0; oi < 9; oi++) acc[mi][oi] = 0ull;

    for (int kc = 0; kc < HID; kc += 16) {
        float4 v0 = *(const float4*)&Abase[(size_t)lr * HID + kc + lk];
        float4 v1 = *(const float4*)&Abase[(size_t)lr * HID + kc + lk + 4];
        pA[lk + 0][lr] = v0.x; pA[lk + 1][lr] = v0.y;
        pA[lk + 2][lr] = v0.z; pA[lk + 3][lr] = v0.w;
        pA[lk + 4][lr] = v1.x; pA[lk + 5][lr] = v1.y;
        pA[lk + 6][lr] = v1.z; pA[lk + 7][lr] = v1.w;
#pragma unroll
        for (int l = 0; l < 9; l++) {
            int lin = tid + 128 * l;
            int k = lin / 72;
            int o = lin - k * 72;
            pW[k][o] = Wpost[o * HID + kc + k];
        }
        __syncthreads();
#pragma unroll
        for (int k = 0; k < 16; k++) {
            float2 av = *(const float2*)&pA[k][m];
            unsigned long long a0 = pack2(av.x, av.x);
            unsigned long long a1 = pack2(av.y, av.y);
#pragma unroll
            for (int oi = 0; oi < 9; oi++) {
                unsigned long long w = *(const unsigned long long*)&pW[k][ob + 2 * oi];
                fma2(acc[0][oi], a0, w);
                fma2(acc[1][oi], a1, w);
            }
        }
        __syncthreads();
    }
#pragma unroll
    for (int mi = 0; mi < 2; mi++) {
        int b = m0 + m + mi;
        float* orow = out + (size_t)b * (TLEN * OUTD) + t * OUTD;
#pragma unroll
        for (int oi = 0; oi < 9; oi++) {
            float x, y;
            unpack2(acc[mi][oi], x, y);
            int o = ob + 2 * oi;
            orow[o]     = x + bpost[o];
            orow[o + 1] = y + bpost[o + 1];
        }
    }
}

// ====================================================================
// kernel_launch
// ====================================================================
extern "C" void kernel_launch(void* const* d_in, const int* in_sizes, int n_in,
                              void* d_out, int out_size) {
    const float* src   = (const float*)d_in[0];
    const float* h0    = (const float*)d_in[2];
    const float* c0    = (const float*)d_in[3];
    const float* Wih   = (const float*)d_in[4];
    const float* Whh   = (const float*)d_in[5];
    const float* bih   = (const float*)d_in[6];
    const float* bhh   = (const float*)d_in[7];
    const float* Wpost = (const float*)d_in[8];
    const float* bpost = (const float*)d_in[9];
    float* out = (float*)d_out;

    cudaFuncSetAttribute(lstm_step_mma, cudaFuncAttributeMaxDynamicSharedMemorySize, DYN_SMEM);

    prepWr   <<<2048, 256>>>(Wih, Whh);
    prepW0k  <<<2048, 256>>>(Wih, Whh);
    prepState<<<2048, 256>>>(src, h0, c0, bih, bhh);

    dim3 sgrid(48, 2);     // 48 N-tiles (64 packed cols = 16 units) x 2 M-tiles -> 96 CTAs
    for (int t = 0; t < TLEN; t++)
        lstm_step_mma<<<sgrid, 256, DYN_SMEM>>>(t);

    dim3 pgrid(TLEN, 4);
    post_proj<<<pgrid, 128>>>(Wpost, bpost, out);
}

// round 15
// speedup vs baseline: 2.5135x; 1.0767x over previous
#include <cuda_runtime.h>
#include <cuda_fp16.h>
#include <math.h>
#include <stdint.h>

// Problem constants
#define BATCH 256
#define HID   768
#define G4    3072
#define TLEN  100
#define OUTD  72
#define SRCL  16
#define BH    (BATCH * HID)

// step-kernel geometry (mma.sync path, base sm_103 target — no tcgen05)
// Gate packing: n = j*4 + g  (4-gate quadruple adjacent -> any N tile mult of 4)
#define STAGE_K   64                  // k per smem stage: 64 fp16 = 128B row
#define A_TILEB   8192                // 64 m-rows x 128B
#define W_TILEB   8192                // 64 n-rows x 128B
#define BUFB      (A_TILEB + W_TILEB) // 16KB per stage
#define GSTRIDE   68                  // gate smem row stride (f32)
#define DYN_SMEM  (1024 + 2 * BUFB)   // 33KB; G tile (64*68*4=17.4KB) fits under

// -------- device scratch (allocation-free: __device__ globals) --------
static __device__ __half g_Wr [G4 * 1536];      // rec W (Wih+Whh): row n -> [wh(768)|wl(768)]
static __device__ __half g_W0 [G4 * 3072];      // t=0 W [Wih|Whh]: row n -> [w0h(1536)|w0l(1536)]
static __device__ __half g_A0b[BATCH * 3072];   // [a0h(1536)|a0l(1536)], a0=[x0|h0]
static __device__ __half g_Ab [2][BATCH * 1536];// h hi/lo ping-pong: row m -> [hh(768)|hl(768)]
static __device__ float g_C[BATCH * HID];       // cell state
static __device__ float g_H[TLEN * BATCH * HID];// fp32 h history (post_proj input)
static __device__ float g_biasPk[G4];           // bias in packed-N layout: n = j*4 + g

// -------- helpers --------
__device__ __forceinline__ uint32_t smem_u32(const void* p) {
    uint32_t a;
    asm("{ .reg .u64 t; cvta.to.shared.u64 t, %1; cvt.u32.u64 %0, t; }" : "=r"(a) : "l"(p));
    return a;
}
#define SWZ128(o) ((o) ^ (((o) >> 3) & 0x70))

__device__ __forceinline__ float sigmoidf_(float x) { return 1.0f / (1.0f + expf(-x)); }

__device__ __forceinline__ void cp_async16(uint32_t dst, const void* src) {
    asm volatile("cp.async.cg.shared.global [%0], [%1], 16;" :: "r"(dst), "l"(src));
}
#define CP_COMMIT()  asm volatile("cp.async.commit_group;" ::: "memory")
#define CP_WAIT(n)   asm volatile("cp.async.wait_group %0;" :: "n"(n) : "memory")

__device__ __forceinline__ void ldsm4(uint32_t* r, uint32_t addr) {
    asm volatile("ldmatrix.sync.aligned.m8n8.x4.shared.b16 {%0,%1,%2,%3}, [%4];"
                 : "=r"(r[0]), "=r"(r[1]), "=r"(r[2]), "=r"(r[3]) : "r"(addr));
}
__device__ __forceinline__ void mma16816(float* c, const uint32_t* a, const uint32_t* b) {
    asm volatile("mma.sync.aligned.m16n8k16.row.col.f32.f16.f16.f32 "
                 "{%0,%1,%2,%3}, {%4,%5,%6,%7}, {%8,%9}, {%0,%1,%2,%3};"
                 : "+f"(c[0]), "+f"(c[1]), "+f"(c[2]), "+f"(c[3])
                 : "r"(a[0]), "r"(a[1]), "r"(a[2]), "r"(a[3]), "r"(b[0]), "r"(b[1]));
}

// f32x2 helpers (post_proj)
__device__ __forceinline__ unsigned long long pack2(float x, float y) {
    unsigned long long r; asm("mov.b64 %0, {%1, %2};" : "=l"(r) : "f"(x), "f"(y)); return r;
}
__device__ __forceinline__ void unpack2(unsigned long long v, float& x, float& y) {
    asm("mov.b64 {%0, %1}, %2;" : "=f"(x), "=f"(y) : "l"(v));
}
__device__ __forceinline__ void fma2(unsigned long long& d, unsigned long long a, unsigned long long b) {
    asm("fma.rn.f32x2 %0, %1, %2, %0;" : "+l"(d) : "l"(a), "l"(b));
}

// original 4H x H weight row from packed-N index: n = j*4 + g -> row = g*768 + j
__device__ __forceinline__ int rowFromN(int n) {
    return (n & 3) * HID + (n >> 2);
}

// ====================================================================
// Prep kernels: fp16 hi/lo packing of weights and initial state
// ====================================================================
__global__ void prepWr(const float* __restrict__ Wih, const float* __restrict__ Whh) {
    const int stride = gridDim.x * blockDim.x;
    for (int idx = blockIdx.x * blockDim.x + threadIdx.x; idx < G4 * HID; idx += stride) {
        int n = idx / HID, k = idx - n * HID;
        int row = rowFromN(n);
        float w = Wih[row * HID + k] + Whh[row * HID + k];
        __half wh = __float2half_rn(w);
        g_Wr[n * 1536 + k]       = wh;
        g_Wr[n * 1536 + 768 + k] = __float2half_rn(w - __half2float(wh));
    }
}
__global__ void prepW0k(const float* __restrict__ Wih, const float* __restrict__ Whh) {
    const int stride = gridDim.x * blockDim.x;
    for (int idx = blockIdx.x * blockDim.x + threadIdx.x; idx < G4 * 1536; idx += stride) {
        int n = idx / 1536, k = idx - n * 1536;
        int row = rowFromN(n);
        float w = (k < HID) ? Wih[row * HID + k] : Whh[row * HID + (k - HID)];
        __half wh = __float2half_rn(w);
        g_W0[n * 3072 + k]        = wh;
        g_W0[n * 3072 + 1536 + k] = __float2half_rn(w - __half2float(wh));
    }
}
__global__ void prepState(const float* __restrict__ src, const float* __restrict__ h0,
                          const float* __restrict__ c0, const float* __restrict__ bih,
                          const float* __restrict__ bhh) {
    const int stride = gridDim.x * blockDim.x;
    const int t0 = blockIdx.x * blockDim.x + threadIdx.x;
    for (int idx = t0; idx < BATCH * 1536; idx += stride) {
        int m = idx / 1536, q = idx - m * 1536;
        float a = (q < HID) ? src[(m * SRCL + (SRCL - 1)) * HID + q] : h0[m * HID + (q - HID)];
        __half ah = __float2half_rn(a);
        g_A0b[m * 3072 + q]        = ah;
        g_A0b[m * 3072 + 1536 + q] = __float2half_rn(a - __half2float(ah));
    }
    for (int idx = t0; idx < BATCH * HID; idx += stride) g_C[idx] = c0[idx];
    for (int idx = t0; idx < G4; idx += stride) {
        int row = rowFromN(idx);
        g_biasPk[idx] = bih[row] + bhh[row];
    }
}

// ====================================================================
// LSTM step via mma.sync. Grid (48 nt, 4 mt) = 192 CTAs, 128 thr (4 warps).
// CTA tile 64m x 64n (16 hidden units x 4 gates); warp tile 32m x 32n (2x2).
// -> 2 independent CTAs per loaded SM: cross-CTA latency hiding for the
//    barrier/ldsm bubbles that kept tensor at 21% with 1 CTA/SM.
// K_eff = 3*kBase fp16-split; cp.async double-buffered 64-k stages.
// ====================================================================
__global__ __launch_bounds__(128) void lstm_step_mma(int t) {
    extern __shared__ char dyn_raw[];
    char* smb = (char*)(((uintptr_t)dyn_raw + 1023) & ~(uintptr_t)1023);

    const int tid  = threadIdx.x;
    const int wid  = tid >> 5;
    const int lane = tid & 31;
    const int nt   = blockIdx.x;
    const int m0   = blockIdx.y * 64;
    const int n0   = nt * 64;

    const __half* Aglob; const __half* Wglob; int kBase;
    if (t == 0) { Aglob = g_A0b; Wglob = g_W0; kBase = 1536; }
    else        { Aglob = g_Ab[t & 1]; Wglob = g_Wr; kBase = 768; }
    const int rowStride = 2 * kBase;
    const int nStages   = (3 * kBase) / STAGE_K;

    // warp tiling: 2x2 warps of 32m x 32n
    const int mwOff = (wid & 1) * 32;
    const int nwOff = (wid >> 1) * 32;

    // fill coords: 16 rows per pass (128 thr x 16B = 2KB = 16 rows)
    const int frow = tid >> 3;          // 0..15
    const int fcb  = (tid & 7) * 16;

    // ldmatrix per-lane coords (same frag mapping as validated R9/R10 kernels)
    const int grp = lane >> 3, lrw = lane & 7;
    const int aRow = ((grp & 1) ? 8 : 0) + lrw;
    const int aKx  = (grp & 2) ? 16 : 0;
    const int bRow = ((grp & 2) ? 8 : 0) + lrw;
    const int bKx  = (grp & 1) ? 16 : 0;

    const uint32_t smb32 = smem_u32(smb);

    float acc[2][4][4];                 // [mf][n8][c]
#pragma unroll
    for (int a = 0; a < 2; a++)
#pragma unroll
        for (int b = 0; b < 4; b++)
#pragma unroll
            for (int c = 0; c < 4; c++) acc[a][b][c] = 0.0f;

    // stage filler: A 4x16B + W 4x16B cp.async per thread into buf (s&1)
    auto fill = [&](int s) {
        const int b = s & 1;
        const uint32_t dA = smb32 + b * BUFB;
        const uint32_t dW = dA + A_TILEB;
        const int segBase = s * STAGE_K;
        const int seg = segBase / kBase;
        const int kk  = segBase - seg * kBase;
        const int aOff = (seg == 1) ? kBase + kk : kk;   // [ah*wh | al*wh | ah*wl]
        const int wOff = (seg == 2) ? kBase + kk : kk;
#pragma unroll
        for (int i = 0; i < 4; i++) {
            int row = frow + 16 * i;    // 0..63
            cp_async16(dA + SWZ128(row * 128 + fcb),
                       (const char*)Aglob + ((size_t)(m0 + row) * rowStride + aOff) * 2 + fcb);
        }
#pragma unroll
        for (int i = 0; i < 4; i++) {
            int row = frow + 16 * i;    // 0..63
            cp_async16(dW + SWZ128(row * 128 + fcb),
                       (const char*)Wglob + ((size_t)(n0 + row) * rowStride + wOff) * 2 + fcb);
        }
    };

    fill(0); CP_COMMIT();

    for (int s = 0; s < nStages; s++) {
        if (s + 1 < nStages) { fill(s + 1); CP_COMMIT(); CP_WAIT(1); }
        else                 { CP_WAIT(0); }
        __syncthreads();

        const uint32_t bA = smb32 + (s & 1) * BUFB;
        const uint32_t bW = bA + A_TILEB;
#pragma unroll
        for (int k16 = 0; k16 < 4; k16++) {
            const int kb = k16 * 32;     // bytes into 128B row
            uint32_t af[2][4];
#pragma unroll
            for (int mf = 0; mf < 2; mf++) {
                int row = mwOff + mf * 16 + aRow;
                ldsm4(af[mf], bA + SWZ128(row * 128 + kb + aKx));
            }
            uint32_t bf[2][4];
#pragma unroll
            for (int nf = 0; nf < 2; nf++) {
                int row = nwOff + nf * 16 + bRow;
                ldsm4(bf[nf], bW + SWZ128(row * 128 + kb + bKx));
            }
#pragma unroll
            for (int mf = 0; mf < 2; mf++) {
                mma16816(acc[mf][0], af[mf], &bf[0][0]);
                mma16816(acc[mf][1], af[mf], &bf[0][2]);
                mma16816(acc[mf][2], af[mf], &bf[1][0]);
                mma16816(acc[mf][3], af[mf], &bf[1][2]);
            }
        }
        __syncthreads();
    }

    // gates -> smem (reuse pipeline smem; all compute done)
    float* G = (float*)smb;
    {
        const int r0 = lane >> 2, c0 = 2 * (lane & 3);
#pragma unroll
        for (int mf = 0; mf < 2; mf++) {
#pragma unroll
            for (int n8 = 0; n8 < 4; n8++) {
                int row = mwOff + mf * 16 + r0;
                int col = nwOff + n8 * 8 + c0;
                *(float2*)&G[row * GSTRIDE + col]       = make_float2(acc[mf][n8][0], acc[mf][n8][1]);
                *(float2*)&G[(row + 8) * GSTRIDE + col] = make_float2(acc[mf][n8][2], acc[mf][n8][3]);
            }
        }
    }
    __syncthreads();

    // fused LSTM pointwise: 64m x 16 units = 1024 cells / 128 thr = 8 each.
    const float* bias = g_biasPk + n0;
    float* Hbase = g_H + (size_t)t * BH;
    __half* AbN = g_Ab[(t + 1) & 1];
    const int j0 = nt * 16;
#pragma unroll
    for (int e = 0; e < 8; e++) {
        int cell = e * 128 + tid;
        int m  = cell >> 4;             // 0..63
        int u  = cell & 15;
        int b  = m0 + m;
        int gj = j0 + u;
        float4 gv = *(const float4*)&G[m * GSTRIDE + u * 4];
        float4 bv = *(const float4*)&bias[u * 4];
        float gi = gv.x + bv.x;
        float gf = gv.y + bv.y;
        float gg = gv.z + bv.z;
        float go = gv.w + bv.w;
        int ci = b * HID + gj;
        float c = sigmoidf_(gf) * g_C[ci] + sigmoidf_(gi) * tanhf(gg);
        g_C[ci] = c;
        float h = sigmoidf_(go) * tanhf(c);
        Hbase[ci] = h;
        __half hh = __float2half_rn(h);
        AbN[(size_t)b * 1536 + gj]       = hh;
        AbN[(size_t)b * 1536 + 768 + gj] = __float2half_rn(h - __half2float(hh));
    }
}

// ====================================================================
// Post projection: out[b][t][o] = H[t][b][:] . W_post[o][:] + b_post[o]
// grid (100 t, 4 mt), 128 threads. Thread tile: 2 m x 18 o (f32x2).
// ====================================================================
__global__ __launch_bounds__(128) void post_proj(const float* __restrict__ Wpost,
                                                 const float* __restrict__ bpost,
                                                 float* __restrict__ out) {
    __shared__ float pA[16][64];
    __shared__ float pW[16][72];

    const int tid = threadIdx.x;
    const int t   = blockIdx.x;
    const int m0  = blockIdx.y * 64;
    const int tm  = tid >> 2;
    const int to  = tid & 3;
    const int m   = 2 * tm;
    const int ob  = 18 * to;
    const int lr  = tid >> 1;
    const int lk  = (tid & 1) * 8;

    const float* __restrict__ Abase = g_H + (size_t)t * BH + (size_t)m0 * HID;

    unsigned long long acc[2][9];
#pragma unroll
    for (int mi = 0; mi < 2; mi++)
#pragma unroll
        for (int oi = 0; oi < 9; oi++) acc[mi][oi] = 0ull;

    for (int kc = 0; kc < HID; kc += 16) {
        float4 v0 = *(const float4*)&Abase[(size_t)lr * HID + kc + lk];
        float4 v1 = *(const float4*)&Abase[(size_t)lr * HID + kc + lk + 4];
        pA[lk + 0][lr] = v0.x; pA[lk + 1][lr] = v0.y;
        pA[lk + 2][lr] = v0.z; pA[lk + 3][lr] = v0.w;
        pA[lk + 4][lr] = v1.x; pA[lk + 5][lr] = v1.y;
        pA[lk + 6][lr] = v1.z; pA[lk + 7][lr] = v1.w;
#pragma unroll
        for (int l = 0; l < 9; l++) {
            int lin = tid + 128 * l;
            int k = lin / 72;
            int o = lin - k * 72;
            pW[k][o] = Wpost[o * HID + kc + k];
        }
        __syncthreads();
#pragma unroll
        for (int k = 0; k < 16; k++) {
            float2 av = *(const float2*)&pA[k][m];
            unsigned long long a0 = pack2(av.x, av.x);
            unsigned long long a1 = pack2(av.y, av.y);
#pragma unroll
            for (int oi = 0; oi < 9; oi++) {
                unsigned long long w = *(const unsigned long long*)&pW[k][ob + 2 * oi];
                fma2(acc[0][oi], a0, w);
                fma2(acc[1][oi], a1, w);
            }
        }
        __syncthreads();
    }
#pragma unroll
    for (int mi = 0; mi < 2; mi++) {
        int b = m0 + m + mi;
        float* orow = out + (size_t)b * (TLEN * OUTD) + t * OUTD;
#pragma unroll
        for (int oi = 0; oi < 9; oi++) {
            float x, y;
            unpack2(acc[mi][oi], x, y);
            int o = ob + 2 * oi;
            orow[o]     = x + bpost[o];
            orow[o + 1] = y + bpost[o + 1];
        }
    }
}

// ====================================================================
// kernel_launch
// ====================================================================
extern "C" void kernel_launch(void* const* d_in, const int* in_sizes, int n_in,
                              void* d_out, int out_size) {
    const float* src   = (const float*)d_in[0];
    const float* h0    = (const float*)d_in[2];
    const float* c0    = (const float*)d_in[3];
    const float* Wih   = (const float*)d_in[4];
    const float* Whh   = (const float*)d_in[5];
    const float* bih   = (const float*)d_in[6];
    const float* bhh   = (const float*)d_in[7];
    const float* Wpost = (const float*)d_in[8];
    const float* bpost = (const float*)d_in[9];
    float* out = (float*)d_out;

    cudaFuncSetAttribute(lstm_step_mma, cudaFuncAttributeMaxDynamicSharedMemorySize, DYN_SMEM);

    prepWr   <<<2048, 256>>>(Wih, Whh);
    prepW0k  <<<2048, 256>>>(Wih, Whh);
    prepState<<<2048, 256>>>(src, h0, c0, bih, bhh);

    dim3 sgrid(48, 4);     // 48 N-tiles x 4 M-tiles = 192 CTAs (2/SM on loaded SMs)
    for (int t = 0; t < TLEN; t++)
        lstm_step_mma<<<sgrid, 128, DYN_SMEM>>>(t);

    dim3 pgrid(TLEN, 4);
    post_proj<<<pgrid, 128>>>(Wpost, bpost, out);
}